// round 12
// baseline (speedup 1.0000x reference)
#include <cuda_runtime.h>

#define DEPTH   8
#define NCLASS  10
#define NT      64
#define NREG    32    // float2 elements per thread; NT*NREG = 2048 = DIM/2

typedef unsigned long long u64;

// GF(2)-linear element swizzle (conflict-free u64 LDS/STS for all patterns).
__device__ __host__ constexpr int Sz(int e) {
    return e ^ ((e >> 5) & 15) ^ (((e >> 10) & 1) << 3);
}
// CNOT-layer composite map in element space: old_e = Emap(new_e).
__device__ __host__ constexpr int Emap(int e) {
    return e ^ (e >> 1) ^ ((e >> 2) & 0x2AA);
}
__device__ __host__ constexpr int CBr(int r)  { return (r << 5) ^ (r & 15); } // Sz(r<<5)
__device__ __host__ constexpr int CGr(int r)  { return Emap(r); }             // Sz(Emap(r)), r<32
__device__ __host__ constexpr bool SWP(int r) { return ((r ^ (r >> 1)) & 1) != 0; }

#define PACK2(d,x,y)   asm("mov.b64 %0,{%1,%2};" : "=l"(d) : "f"(x),"f"(y))
#define UNPACK2(x,y,d) asm("mov.b64 {%0,%1},%2;" : "=f"(x),"=f"(y) : "l"(d))
#define MUL2(d,a,b)    asm("mul.rn.f32x2 %0,%1,%2;" : "=l"(d) : "l"(a),"l"(b))
#define FMA2(d,a,b,c)  asm("fma.rn.f32x2 %0,%1,%2,%3;" : "=l"(d) : "l"(a),"l"(b),"l"(c))

// Scaled-shear RY butterfly on 32 u64 regs along register-bit mask m.
// Both FMAs independent (chain depth 1 per qubit). Cos factors are NOT
// applied here — the product of all 96 cos factors is applied once to
// the final probabilities (global scalar, commutes with everything).
__device__ __forceinline__ void shear32(u64* P, int m, u64 T2, u64 NT2) {
#pragma unroll
    for (int k = 0; k < NREG; k++)
        if (!(k & m)) {
            u64 n0, n1;
            FMA2(n0, NT2, P[k | m], P[k]);     // b0 = a0 - p*a1
            FMA2(n1, T2,  P[k],     P[k | m]); // b1 = a1 + p*a0
            P[k]     = n0;
            P[k | m] = n1;
        }
}

__global__ __launch_bounds__(NT, 8) void vqc_kernel(const float* __restrict__ X,
                                                    const float* __restrict__ W,
                                                    float* __restrict__ out) {
    __shared__ u64 smB[2048];                         // SINGLE statevector buffer
    __shared__ u64 TT2[DEPTH * 12], NT2s[DEPTH * 12]; // packed tan / -tan
    __shared__ float t0s[DEPTH];                      // scalar tan, qubit 0
    __shared__ float t11s[DEPTH];                     // scalar tan, qubit 11
    __shared__ float CTOT2;                           // (prod of all cos)^2
    __shared__ float enc0[12], enc1[12];
    __shared__ float red[2][NCLASS];

    const int t = threadIdx.x;

    // ---- coefficient tables ----
    for (int i = t; i < DEPTH * 12; i += NT) {
        float s_, c_;
        sincosf(0.5f * W[i], &s_, &c_);
        float tp = s_ / c_;                   // tan(phi/2)
        float nt = -tp;
        u64 a, b;
        PACK2(a, tp, tp);  PACK2(b, nt, nt);
        TT2[i] = a;  NT2s[i] = b;
        const int q = i % 12, k = i / 12;
        if (q == 0)  t0s[k]  = tp;
        if (q == 11) t11s[k] = tp;
    }
    if (t == 0) {                             // global cos product (squared)
        float C = 1.0f;
#pragma unroll
        for (int i = 0; i < DEPTH * 12; i++)
            C *= cosf(0.5f * W[i]);
        CTOT2 = C * C;
    }
    if (t < 12) {
        float s_, c_;
        sincosf(0.5f * X[blockIdx.x * 12 + t], &s_, &c_);
        const float rr = 0.7071067811865476f;
        enc0[t] = (c_ - s_) * rr;
        enc1[t] = (c_ + s_) * rr;
    }
    __syncthreads();

    // ---- per-thread address bases (all maps GF(2)-linear) ----
    // Tiling A: e = (t<<5)|r   (regs = e4..0 -> qubits 6..10)
    // Tiling B: e = (t0<<10)|(r<<5)|((t>>1)&31)  (regs = e9..5 -> qubits 1..5)
    const int bA = (t << 5) ^ (t & 15) ^ (((t >> 5) & 1) << 3);
    const int bB = (((t & 1) << 10) | ((t >> 1) & 31)) ^ ((t & 1) << 3);
    int em = t << 5;
    em = em ^ (em >> 1) ^ ((em >> 2) & 0x2AA);
    const int bG = Sz(em);

    // ---- init: product state (H + encoding RY) in tiling B registers ----
    // thread bits: q0<-t0, q6<-t5, q7<-t4, q8<-t3, q9<-t2, q10<-t1
    float base = (t & 1)        ? enc1[0]  : enc0[0];
    base *= ((t >> 5) & 1)      ? enc1[6]  : enc0[6];
    base *= ((t >> 4) & 1)      ? enc1[7]  : enc0[7];
    base *= ((t >> 3) & 1)      ? enc1[8]  : enc0[8];
    base *= ((t >> 2) & 1)      ? enc1[9]  : enc0[9];
    base *= ((t >> 1) & 1)      ? enc1[10] : enc0[10];
    const float bx = base * enc0[11], by = base * enc1[11];

    u64 P[NREG];
#pragma unroll
    for (int r = 0; r < NREG; r++) {
        // reg bits: q1<-r4, q2<-r3, q3<-r2, q4<-r1, q5<-r0
        float rf = (r & 16) ? enc1[1] : enc0[1];
        rf *= (r & 8) ? enc1[2] : enc0[2];
        rf *= (r & 4) ? enc1[3] : enc0[3];
        rf *= (r & 2) ? enc1[4] : enc0[4];
        rf *= (r & 1) ? enc1[5] : enc0[5];
        float x = rf * bx, y = rf * by;
        PACK2(P[r], x, y);
    }

#pragma unroll 1
    for (int k = 0; k < DEPTH; k++) {
        const int kc = k * 12;

        // ---- trip 1: store B -> gather + q11 shear -> q10..q6 shears ----
        // store-B writes the same per-thread address set that this thread's
        // previous load-B read -> intra-thread WAR only, no barrier needed.
#pragma unroll
        for (int r = 0; r < NREG; r++)
            smB[bB ^ CBr(r)] = P[r];
        __syncthreads();                       // store-B visible before gather

        const float t11 = t11s[k];
#pragma unroll
        for (int r = 0; r < NREG; r++) {
            float2 L = ((const float2*)smB)[bG ^ CGr(r)];
            float x = SWP(r) ? L.y : L.x;
            float y = SWP(r) ? L.x : L.y;
            // SIMD qubit 11: shear (both FMAs independent)
            float u = fmaf(-t11, y, x);
            float v = fmaf( t11, x, y);
            PACK2(P[r], u, v);
        }
        __syncthreads();                       // gather reads done before store-A
        // fine -> coarse: mask-1 shear only needs adjacent pairs, so its FMAs
        // can start while later gather loads are still in flight.
        shear32(P, 1,  TT2[kc + 10], NT2s[kc + 10]);  // q10 <-> r0
        shear32(P, 2,  TT2[kc + 9],  NT2s[kc + 9]);   // q9
        shear32(P, 4,  TT2[kc + 8],  NT2s[kc + 8]);   // q8
        shear32(P, 8,  TT2[kc + 7],  NT2s[kc + 7]);   // q7
        shear32(P, 16, TT2[kc + 6],  NT2s[kc + 6]);   // q6  <-> r4

        // ---- trip 2: store A -> load B (transpose) -> q5..q1 + shfl q0 ----
#pragma unroll
        for (int r = 0; r < NREG; r++)
            smB[bA ^ r] = P[r];
        __syncthreads();                       // store-A visible before load-B
#pragma unroll
        for (int r = 0; r < NREG; r++)
            P[r] = smB[bB ^ CBr(r)];

        shear32(P, 1,  TT2[kc + 5], NT2s[kc + 5]);    // q5 <-> r0
        shear32(P, 2,  TT2[kc + 4], NT2s[kc + 4]);
        shear32(P, 4,  TT2[kc + 3], NT2s[kc + 3]);
        shear32(P, 8,  TT2[kc + 2], NT2s[kc + 2]);
        shear32(P, 16, TT2[kc + 1], NT2s[kc + 1]);    // q1 <-> r4

        // qubit 0 on lane bit t0: shear via shfl (1 FMA2 per reg)
        {
            const float t0c = t0s[k];
            const float te = (t & 1) ? t0c : -t0c;
            u64 TE2;
            PACK2(TE2, te, te);
#pragma unroll
            for (int r = 0; r < NREG; r++) {
                u64 part = __shfl_xor_sync(0xffffffffu, P[r], 1);
                FMA2(P[r], TE2, part, P[r]);   // b = a ± p*partner
            }
        }
    }

    // ---- measurement from registers (tiling B) ----
    float T = 0.0f, A1 = 0.0f, A2 = 0.0f, A3 = 0.0f, A4 = 0.0f, A5 = 0.0f;
#pragma unroll
    for (int r = 0; r < NREG; r++) {
        float x, y;
        UNPACK2(x, y, P[r]);
        float p2 = fmaf(y, y, x * x);
        T += p2;
        if (!(r & 16)) A1 += p2;
        if (!(r & 8))  A2 += p2;
        if (!(r & 4))  A3 += p2;
        if (!(r & 2))  A4 += p2;
        if (!(r & 1))  A5 += p2;
    }
    float loc[NCLASS];
    loc[0] = (t & 1)        ? -T : T;
    loc[1] = 2.0f * A1 - T;
    loc[2] = 2.0f * A2 - T;
    loc[3] = 2.0f * A3 - T;
    loc[4] = 2.0f * A4 - T;
    loc[5] = 2.0f * A5 - T;
    loc[6] = ((t >> 5) & 1) ? -T : T;
    loc[7] = ((t >> 4) & 1) ? -T : T;
    loc[8] = ((t >> 3) & 1) ? -T : T;
    loc[9] = ((t >> 2) & 1) ? -T : T;

#pragma unroll
    for (int p = 0; p < NCLASS; p++) {
        float v = loc[p];
#pragma unroll
        for (int o = 16; o > 0; o >>= 1)
            v += __shfl_xor_sync(0xffffffffu, v, o);
        if ((t & 31) == 0) red[t >> 5][p] = v;
    }
    __syncthreads();
    if (t < NCLASS)
        out[blockIdx.x * NCLASS + t] = (red[0][t] + red[1][t]) * CTOT2;
}

extern "C" void kernel_launch(void* const* d_in, const int* in_sizes, int n_in,
                              void* d_out, int out_size) {
    const float* X = (const float*)d_in[0];   // [4096, 12] fp32
    const float* W = (const float*)d_in[1];   // [8, 12]    fp32
    float* out = (float*)d_out;               // [4096, 10] fp32
    const int batch = in_sizes[0] / 12;
    vqc_kernel<<<batch, NT>>>(X, W, out);
}

// round 13
// speedup vs baseline: 1.8106x; 1.8106x over previous
#include <cuda_runtime.h>

#define DEPTH   8
#define NCLASS  10
#define NT      64
#define NREG    32    // float2 elements per thread; NT*NREG = 2048 = DIM/2

typedef unsigned long long u64;

// GF(2)-linear element swizzle (conflict-free u64 LDS/STS for all patterns).
__device__ __host__ constexpr int Sz(int e) {
    return e ^ ((e >> 5) & 15) ^ (((e >> 10) & 1) << 3);
}
// CNOT-layer composite map in element space: old_e = Emap(new_e).
__device__ __host__ constexpr int Emap(int e) {
    return e ^ (e >> 1) ^ ((e >> 2) & 0x2AA);
}
__device__ __host__ constexpr int CBr(int r)  { return (r << 5) ^ (r & 15); } // Sz(r<<5)
__device__ __host__ constexpr int CGr(int r)  { return Emap(r); }             // Sz(Emap(r)), r<32
__device__ __host__ constexpr bool SWP(int r) { return ((r ^ (r >> 1)) & 1) != 0; }

#define PACK2(d,x,y)   asm("mov.b64 %0,{%1,%2};" : "=l"(d) : "f"(x),"f"(y))
#define UNPACK2(x,y,d) asm("mov.b64 {%0,%1},%2;" : "=f"(x),"=f"(y) : "l"(d))
#define MUL2(d,a,b)    asm("mul.rn.f32x2 %0,%1,%2;" : "=l"(d) : "l"(a),"l"(b))
#define FMA2(d,a,b,c)  asm("fma.rn.f32x2 %0,%1,%2,%3;" : "=l"(d) : "l"(a),"l"(b),"l"(c))

// Scaled-shear RY butterfly on 32 u64 regs along register-bit mask m.
// Both FMAs independent (chain depth 1 per qubit). Cos factors are NOT
// applied here — the product of all 96 cos factors is applied once to
// the final probabilities (global scalar, commutes with everything).
__device__ __forceinline__ void shear32(u64* P, int m, u64 T2, u64 NT2) {
#pragma unroll
    for (int k = 0; k < NREG; k++)
        if (!(k & m)) {
            u64 n0, n1;
            FMA2(n0, NT2, P[k | m], P[k]);     // b0 = a0 - p*a1
            FMA2(n1, T2,  P[k],     P[k | m]); // b1 = a1 + p*a0
            P[k]     = n0;
            P[k | m] = n1;
        }
}

__global__ __launch_bounds__(NT, 8) void vqc_kernel(const float* __restrict__ X,
                                                    const float* __restrict__ W,
                                                    float* __restrict__ out) {
    __shared__ u64 smB[2048];                         // SINGLE statevector buffer
    __shared__ u64 TT2[DEPTH * 12], NT2s[DEPTH * 12]; // packed tan / -tan
    __shared__ float t0s[DEPTH];                      // scalar tan, qubit 0
    __shared__ float t11s[DEPTH];                     // scalar tan, qubit 11
    __shared__ float cosv[DEPTH * 12];                // per-gate cos (parallel)
    __shared__ float enc0[12], enc1[12];
    __shared__ float red[2][NCLASS];

    const int t = threadIdx.x;

    // ---- coefficient tables (cos values stored in PARALLEL; the global
    //      product is a cheap multiply-reduction at the end) ----
    for (int i = t; i < DEPTH * 12; i += NT) {
        float s_, c_;
        sincosf(0.5f * W[i], &s_, &c_);
        float tp = s_ / c_;                   // tan(phi/2)
        float nt = -tp;
        u64 a, b;
        PACK2(a, tp, tp);  PACK2(b, nt, nt);
        TT2[i] = a;  NT2s[i] = b;
        cosv[i] = c_;
        const int q = i % 12, k = i / 12;
        if (q == 0)  t0s[k]  = tp;
        if (q == 11) t11s[k] = tp;
    }
    if (t < 12) {
        float s_, c_;
        sincosf(0.5f * X[blockIdx.x * 12 + t], &s_, &c_);
        const float rr = 0.7071067811865476f;
        enc0[t] = (c_ - s_) * rr;
        enc1[t] = (c_ + s_) * rr;
    }
    __syncthreads();

    // ---- per-thread address bases (all maps GF(2)-linear) ----
    // Tiling A: e = (t<<5)|r   (regs = e4..0 -> qubits 6..10)
    // Tiling B: e = (t0<<10)|(r<<5)|((t>>1)&31)  (regs = e9..5 -> qubits 1..5)
    const int bA = (t << 5) ^ (t & 15) ^ (((t >> 5) & 1) << 3);
    const int bB = (((t & 1) << 10) | ((t >> 1) & 31)) ^ ((t & 1) << 3);
    int em = t << 5;
    em = em ^ (em >> 1) ^ ((em >> 2) & 0x2AA);
    const int bG = Sz(em);

    // ---- init: product state (H + encoding RY) in tiling B registers ----
    // thread bits: q0<-t0, q6<-t5, q7<-t4, q8<-t3, q9<-t2, q10<-t1
    float base = (t & 1)        ? enc1[0]  : enc0[0];
    base *= ((t >> 5) & 1)      ? enc1[6]  : enc0[6];
    base *= ((t >> 4) & 1)      ? enc1[7]  : enc0[7];
    base *= ((t >> 3) & 1)      ? enc1[8]  : enc0[8];
    base *= ((t >> 2) & 1)      ? enc1[9]  : enc0[9];
    base *= ((t >> 1) & 1)      ? enc1[10] : enc0[10];
    const float bx = base * enc0[11], by = base * enc1[11];

    u64 P[NREG];
#pragma unroll
    for (int r = 0; r < NREG; r++) {
        // reg bits: q1<-r4, q2<-r3, q3<-r2, q4<-r1, q5<-r0
        float rf = (r & 16) ? enc1[1] : enc0[1];
        rf *= (r & 8) ? enc1[2] : enc0[2];
        rf *= (r & 4) ? enc1[3] : enc0[3];
        rf *= (r & 2) ? enc1[4] : enc0[4];
        rf *= (r & 1) ? enc1[5] : enc0[5];
        float x = rf * bx, y = rf * by;
        PACK2(P[r], x, y);
    }

#pragma unroll 1
    for (int k = 0; k < DEPTH; k++) {
        const int kc = k * 12;

        // ---- trip 1: store B -> gather + q11 shear -> q6..q10 shears ----
        // store-B writes the same per-thread address set that this thread's
        // previous load-B read -> intra-thread WAR only, no barrier needed.
#pragma unroll
        for (int r = 0; r < NREG; r++)
            smB[bB ^ CBr(r)] = P[r];
        __syncthreads();                       // store-B visible before gather

        const float t11 = t11s[k];
#pragma unroll
        for (int r = 0; r < NREG; r++) {
            float2 L = ((const float2*)smB)[bG ^ CGr(r)];
            float x = SWP(r) ? L.y : L.x;
            float y = SWP(r) ? L.x : L.y;
            // SIMD qubit 11: shear (both FMAs independent)
            float u = fmaf(-t11, y, x);
            float v = fmaf( t11, x, y);
            PACK2(P[r], u, v);
        }
        __syncthreads();                       // gather reads done before store-A
        shear32(P, 16, TT2[kc + 6],  NT2s[kc + 6]);   // q6  <-> r4 (R11 order)
        shear32(P, 8,  TT2[kc + 7],  NT2s[kc + 7]);   // q7
        shear32(P, 4,  TT2[kc + 8],  NT2s[kc + 8]);   // q8
        shear32(P, 2,  TT2[kc + 9],  NT2s[kc + 9]);   // q9
        shear32(P, 1,  TT2[kc + 10], NT2s[kc + 10]);  // q10

        // ---- trip 2: store A -> load B (transpose) -> q1..q5 + shfl q0 ----
#pragma unroll
        for (int r = 0; r < NREG; r++)
            smB[bA ^ r] = P[r];
        __syncthreads();                       // store-A visible before load-B
#pragma unroll
        for (int r = 0; r < NREG; r++)
            P[r] = smB[bB ^ CBr(r)];

        shear32(P, 16, TT2[kc + 1], NT2s[kc + 1]);    // q1 <-> r4
        shear32(P, 8,  TT2[kc + 2], NT2s[kc + 2]);
        shear32(P, 4,  TT2[kc + 3], NT2s[kc + 3]);
        shear32(P, 2,  TT2[kc + 4], NT2s[kc + 4]);
        shear32(P, 1,  TT2[kc + 5], NT2s[kc + 5]);

        // qubit 0 on lane bit t0: shear via shfl (1 FMA2 per reg)
        {
            const float t0c = t0s[k];
            const float te = (t & 1) ? t0c : -t0c;
            u64 TE2;
            PACK2(TE2, te, te);
#pragma unroll
            for (int r = 0; r < NREG; r++) {
                u64 part = __shfl_xor_sync(0xffffffffu, P[r], 1);
                FMA2(P[r], TE2, part, P[r]);   // b = a ± p*partner
            }
        }
    }

    // ---- measurement from registers (tiling B) ----
    float T = 0.0f, A1 = 0.0f, A2 = 0.0f, A3 = 0.0f, A4 = 0.0f, A5 = 0.0f;
#pragma unroll
    for (int r = 0; r < NREG; r++) {
        float x, y;
        UNPACK2(x, y, P[r]);
        float p2 = fmaf(y, y, x * x);
        T += p2;
        if (!(r & 16)) A1 += p2;
        if (!(r & 8))  A2 += p2;
        if (!(r & 4))  A3 += p2;
        if (!(r & 2))  A4 += p2;
        if (!(r & 1))  A5 += p2;
    }
    // global cos-product correction: cheap multiply reduction from shared
    // (values already computed in parallel by the table loop)
    float CT = 1.0f;
#pragma unroll
    for (int i = 0; i < DEPTH * 12; i++)
        CT *= cosv[i];
    const float CT2 = CT * CT;
    T *= CT2;  A1 *= CT2;  A2 *= CT2;  A3 *= CT2;  A4 *= CT2;  A5 *= CT2;

    float loc[NCLASS];
    loc[0] = (t & 1)        ? -T : T;
    loc[1] = 2.0f * A1 - T;
    loc[2] = 2.0f * A2 - T;
    loc[3] = 2.0f * A3 - T;
    loc[4] = 2.0f * A4 - T;
    loc[5] = 2.0f * A5 - T;
    loc[6] = ((t >> 5) & 1) ? -T : T;
    loc[7] = ((t >> 4) & 1) ? -T : T;
    loc[8] = ((t >> 3) & 1) ? -T : T;
    loc[9] = ((t >> 2) & 1) ? -T : T;

#pragma unroll
    for (int p = 0; p < NCLASS; p++) {
        float v = loc[p];
#pragma unroll
        for (int o = 16; o > 0; o >>= 1)
            v += __shfl_xor_sync(0xffffffffu, v, o);
        if ((t & 31) == 0) red[t >> 5][p] = v;
    }
    __syncthreads();
    if (t < NCLASS)
        out[blockIdx.x * NCLASS + t] = red[0][t] + red[1][t];
}

extern "C" void kernel_launch(void* const* d_in, const int* in_sizes, int n_in,
                              void* d_out, int out_size) {
    const float* X = (const float*)d_in[0];   // [4096, 12] fp32
    const float* W = (const float*)d_in[1];   // [8, 12]    fp32
    float* out = (float*)d_out;               // [4096, 10] fp32
    const int batch = in_sizes[0] / 12;
    vqc_kernel<<<batch, NT>>>(X, W, out);
}